// round 2
// baseline (speedup 1.0000x reference)
#include <cuda_runtime.h>
#include <math.h>

#define H 4096
#define IDIM 5632
#define NE 8
#define T 4096
#define NTOPK 2
#define NSLOTS (T * NTOPK)

// ---------------- scratch (device globals; allocation-free) ----------------
__device__ float g_act[(size_t)NSLOTS * IDIM];   // silu(g)*u activations, expert-sorted slots
__device__ int   g_counts[NE];
__device__ int   g_offsets[NE];
__device__ int   g_cursor[NE];
__device__ int   g_topi[T * NTOPK];
__device__ float g_topw[T * NTOPK];
__device__ int   g_tok[NSLOTS];                  // slot -> token
__device__ float g_sw[NSLOTS];                   // slot -> routing weight
__device__ float g_psum[NE];                     // sum of softmax probs per expert
__device__ float g_zsum;                         // sum of lse^2

// ---------------- reset ----------------
__global__ void reset_kernel() {
    int i = threadIdx.x;
    if (i < NE) { g_counts[i] = 0; g_cursor[i] = 0; g_psum[i] = 0.f; }
    if (i == 0) g_zsum = 0.f;
}

// ---------------- router: logits, softmax, top-2, aux stats ----------------
__global__ void router_kernel(const float* __restrict__ x,
                              const float* __restrict__ Wgate) {
    int t = blockIdx.x;
    const float* xr = x + (size_t)t * H;
    float p[NE];
#pragma unroll
    for (int e = 0; e < NE; ++e) p[e] = 0.f;

    for (int c = threadIdx.x; c < H; c += blockDim.x) {
        float xv = xr[c];
#pragma unroll
        for (int e = 0; e < NE; ++e) p[e] += xv * Wgate[e * H + c];
    }

    __shared__ float sm[NE][128];
#pragma unroll
    for (int e = 0; e < NE; ++e) sm[e][threadIdx.x] = p[e];
    __syncthreads();
    for (int s = 64; s > 0; s >>= 1) {
        if (threadIdx.x < s) {
#pragma unroll
            for (int e = 0; e < NE; ++e)
                sm[e][threadIdx.x] += sm[e][threadIdx.x + s];
        }
        __syncthreads();
    }

    if (threadIdx.x == 0) {
        float lg[NE];
#pragma unroll
        for (int e = 0; e < NE; ++e) lg[e] = sm[e][0];
        float mx = lg[0];
#pragma unroll
        for (int e = 1; e < NE; ++e) mx = fmaxf(mx, lg[e]);
        float se = 0.f, pr[NE];
#pragma unroll
        for (int e = 0; e < NE; ++e) { pr[e] = expf(lg[e] - mx); se += pr[e]; }
        float inv = 1.f / se;
#pragma unroll
        for (int e = 0; e < NE; ++e) pr[e] *= inv;

        // top-2 (lowest index wins ties, matching lax.top_k)
        int i0 = 0;
#pragma unroll
        for (int e = 1; e < NE; ++e) if (pr[e] > pr[i0]) i0 = e;
        int i1 = (i0 == 0) ? 1 : 0;
#pragma unroll
        for (int e = 0; e < NE; ++e)
            if (e != i0 && pr[e] > pr[i1]) i1 = e;

        float w0 = pr[i0], w1 = pr[i1];
        float ws = 1.f / (w0 + w1);
        w0 *= ws; w1 *= ws;

        g_topi[2 * t + 0] = i0; g_topw[2 * t + 0] = w0;
        g_topi[2 * t + 1] = i1; g_topw[2 * t + 1] = w1;
        atomicAdd(&g_counts[i0], 1);
        atomicAdd(&g_counts[i1], 1);
#pragma unroll
        for (int e = 0; e < NE; ++e) atomicAdd(&g_psum[e], pr[e]);
        float lse = mx + logf(se);
        atomicAdd(&g_zsum, lse * lse);
    }
}

// ---------------- finalize: offsets + aux scalar ----------------
__global__ void finalize_kernel(float* __restrict__ out, int out_size) {
    if (threadIdx.x == 0 && blockIdx.x == 0) {
        int off = 0;
        for (int e = 0; e < NE; ++e) {
            g_offsets[e] = off;
            g_cursor[e] = off;
            off += g_counts[e];
        }
        float aux = 0.f;
        for (int e = 0; e < NE; ++e) {
            float pm = g_psum[e] / (float)T;
            float fr = (float)g_counts[e] / (float)(T * NTOPK);
            aux += pm * fr;
        }
        aux *= (float)NE;
        float z = g_zsum / (float)T;
        float total = 0.02f * aux + 0.001f * z;
        if (out_size > T * H) out[(size_t)T * H] = total;
    }
}

// ---------------- slot assignment ----------------
__global__ void assign_kernel() {
    int t = blockIdx.x * blockDim.x + threadIdx.x;
    if (t >= T) return;
#pragma unroll
    for (int k = 0; k < NTOPK; ++k) {
        int e = g_topi[2 * t + k];
        int s = atomicAdd(&g_cursor[e], 1);
        g_tok[s] = t;
        g_sw[s] = g_topw[2 * t + k];
    }
}

// ---------------- GEMM1: act = silu(X_e @ Wg[e]^T) * (X_e @ Wu[e]^T) -------
// BM=128, BN=64, BK=16, 256 threads; dual accumulator (gate+up)
#define BM 128
#define BN 64
#define BK 16

__global__ __launch_bounds__(256)
void gemm1_kernel(const float* __restrict__ x,
                  const float* __restrict__ Wg,
                  const float* __restrict__ Wu) {
    int e = blockIdx.z;
    int cnt = g_counts[e];
    int m0 = blockIdx.x * BM;
    if (m0 >= cnt) return;
    int base = g_offsets[e];
    int n0 = blockIdx.y * BN;

    const float* Bgp = Wg + (size_t)e * IDIM * H + (size_t)n0 * H;
    const float* Bup = Wu + (size_t)e * IDIM * H + (size_t)n0 * H;

    __shared__ float As[BK][BM + 4];
    __shared__ float Bgs[BK][BN + 4];
    __shared__ float Bus[BK][BN + 4];

    int tid = threadIdx.x;
    int kq = tid & 3;               // which float4 within the 16-wide k slab
    int ar0 = tid >> 2;             // A rows: tid/4 and tid/4 + 64
    int ar1 = ar0 + 64;
    int brow = tid >> 2;            // B row 0..63

    // Row pointers (gathered tokens); null => zero-fill
    const float* ap0 = nullptr;
    const float* ap1 = nullptr;
    if (m0 + ar0 < cnt) ap0 = x + (size_t)g_tok[base + m0 + ar0] * H + kq * 4;
    if (m0 + ar1 < cnt) ap1 = x + (size_t)g_tok[base + m0 + ar1] * H + kq * 4;
    const float* bgp = Bgp + (size_t)brow * H + kq * 4;
    const float* bup = Bup + (size_t)brow * H + kq * 4;

    int tx = tid & 15;              // n sub 0..15 (4 cols each)
    int ty = tid >> 4;              // m sub 0..15 (8 rows each)

    float accg[8][4], accu[8][4];
#pragma unroll
    for (int i = 0; i < 8; ++i)
#pragma unroll
        for (int j = 0; j < 4; ++j) { accg[i][j] = 0.f; accu[i][j] = 0.f; }

    for (int k0 = 0; k0 < H; k0 += BK) {
        float4 a0 = make_float4(0.f, 0.f, 0.f, 0.f);
        float4 a1 = make_float4(0.f, 0.f, 0.f, 0.f);
        if (ap0) a0 = *(const float4*)(ap0 + k0);
        if (ap1) a1 = *(const float4*)(ap1 + k0);
        float4 bg = *(const float4*)(bgp + k0);
        float4 bu = *(const float4*)(bup + k0);

        As[kq * 4 + 0][ar0] = a0.x; As[kq * 4 + 1][ar0] = a0.y;
        As[kq * 4 + 2][ar0] = a0.z; As[kq * 4 + 3][ar0] = a0.w;
        As[kq * 4 + 0][ar1] = a1.x; As[kq * 4 + 1][ar1] = a1.y;
        As[kq * 4 + 2][ar1] = a1.z; As[kq * 4 + 3][ar1] = a1.w;
        Bgs[kq * 4 + 0][brow] = bg.x; Bgs[kq * 4 + 1][brow] = bg.y;
        Bgs[kq * 4 + 2][brow] = bg.z; Bgs[kq * 4 + 3][brow] = bg.w;
        Bus[kq * 4 + 0][brow] = bu.x; Bus[kq * 4 + 1][brow] = bu.y;
        Bus[kq * 4 + 2][brow] = bu.z; Bus[kq * 4 + 3][brow] = bu.w;
        __syncthreads();

#pragma unroll
        for (int k = 0; k < BK; ++k) {
            float av[8];
#pragma unroll
            for (int i = 0; i < 8; ++i) av[i] = As[k][ty * 8 + i];
            float bgv[4], buv[4];
#pragma unroll
            for (int j = 0; j < 4; ++j) {
                bgv[j] = Bgs[k][tx * 4 + j];
                buv[j] = Bus[k][tx * 4 + j];
            }
#pragma unroll
            for (int i = 0; i < 8; ++i)
#pragma unroll
                for (int j = 0; j < 4; ++j) {
                    accg[i][j] = fmaf(av[i], bgv[j], accg[i][j]);
                    accu[i][j] = fmaf(av[i], buv[j], accu[i][j]);
                }
        }
        __syncthreads();
    }

    // epilogue: silu(g)*u -> act scratch
#pragma unroll
    for (int i = 0; i < 8; ++i) {
        int r = m0 + ty * 8 + i;
        if (r < cnt) {
            float* dst = g_act + (size_t)(base + r) * IDIM + n0 + tx * 4;
            float4 v;
            float g0 = accg[i][0], g1 = accg[i][1], g2 = accg[i][2], g3 = accg[i][3];
            v.x = (g0 / (1.f + expf(-g0))) * accu[i][0];
            v.y = (g1 / (1.f + expf(-g1))) * accu[i][1];
            v.z = (g2 / (1.f + expf(-g2))) * accu[i][2];
            v.w = (g3 / (1.f + expf(-g3))) * accu[i][3];
            *(float4*)dst = v;
        }
    }
}

// ---------------- GEMM2: out[tok] += w * (act_e @ Wd[e]^T) ------------------
__global__ __launch_bounds__(256)
void gemm2_kernel(const float* __restrict__ Wd, float* __restrict__ out) {
    int e = blockIdx.z;
    int cnt = g_counts[e];
    int m0 = blockIdx.x * BM;
    if (m0 >= cnt) return;
    int base = g_offsets[e];
    int n0 = blockIdx.y * BN;

    const float* Bp = Wd + (size_t)e * H * IDIM + (size_t)n0 * IDIM;

    __shared__ float As[BK][BM + 4];
    __shared__ float Bs[BK][BN + 4];

    int tid = threadIdx.x;
    int kq = tid & 3;
    int ar0 = tid >> 2;
    int ar1 = ar0 + 64;
    int brow = tid >> 2;

    const float* ap0 = nullptr;
    const float* ap1 = nullptr;
    if (m0 + ar0 < cnt) ap0 = g_act + (size_t)(base + m0 + ar0) * IDIM + kq * 4;
    if (m0 + ar1 < cnt) ap1 = g_act + (size_t)(base + m0 + ar1) * IDIM + kq * 4;
    const float* bp = Bp + (size_t)brow * IDIM + kq * 4;

    int tx = tid & 15;
    int ty = tid >> 4;

    float acc[8][4];
#pragma unroll
    for (int i = 0; i < 8; ++i)
#pragma unroll
        for (int j = 0; j < 4; ++j) acc[i][j] = 0.f;

    for (int k0 = 0; k0 < IDIM; k0 += BK) {
        float4 a0 = make_float4(0.f, 0.f, 0.f, 0.f);
        float4 a1 = make_float4(0.f, 0.f, 0.f, 0.f);
        if (ap0) a0 = *(const float4*)(ap0 + k0);
        if (ap1) a1 = *(const float4*)(ap1 + k0);
        float4 b = *(const float4*)(bp + k0);

        As[kq * 4 + 0][ar0] = a0.x; As[kq * 4 + 1][ar0] = a0.y;
        As[kq * 4 + 2][ar0] = a0.z; As[kq * 4 + 3][ar0] = a0.w;
        As[kq * 4 + 0][ar1] = a1.x; As[kq * 4 + 1][ar1] = a1.y;
        As[kq * 4 + 2][ar1] = a1.z; As[kq * 4 + 3][ar1] = a1.w;
        Bs[kq * 4 + 0][brow] = b.x; Bs[kq * 4 + 1][brow] = b.y;
        Bs[kq * 4 + 2][brow] = b.z; Bs[kq * 4 + 3][brow] = b.w;
        __syncthreads();

#pragma unroll
        for (int k = 0; k < BK; ++k) {
            float av[8];
#pragma unroll
            for (int i = 0; i < 8; ++i) av[i] = As[k][ty * 8 + i];
            float bv[4];
#pragma unroll
            for (int j = 0; j < 4; ++j) bv[j] = Bs[k][tx * 4 + j];
#pragma unroll
            for (int i = 0; i < 8; ++i)
#pragma unroll
                for (int j = 0; j < 4; ++j)
                    acc[i][j] = fmaf(av[i], bv[j], acc[i][j]);
        }
        __syncthreads();
    }

#pragma unroll
    for (int i = 0; i < 8; ++i) {
        int r = m0 + ty * 8 + i;
        if (r < cnt) {
            int s = base + r;
            int tok = g_tok[s];
            float w = g_sw[s];
            float* dst = out + (size_t)tok * H + n0 + tx * 4;
#pragma unroll
            for (int j = 0; j < 4; ++j)
                atomicAdd(dst + j, w * acc[i][j]);
        }
    }
}

// ---------------- launch ----------------
extern "C" void kernel_launch(void* const* d_in, const int* in_sizes, int n_in,
                              void* d_out, int out_size) {
    const float* x     = (const float*)d_in[0];   // [2,2048,H] fp32
    const float* Wgate = (const float*)d_in[1];   // [E,H]
    const float* Wg    = (const float*)d_in[2];   // [E,I,H]
    const float* Wu    = (const float*)d_in[3];   // [E,I,H]
    const float* Wd    = (const float*)d_in[4];   // [E,H,I]
    float* out = (float*)d_out;

    cudaMemsetAsync(out, 0, (size_t)out_size * sizeof(float));
    reset_kernel<<<1, 32>>>();
    router_kernel<<<T, 128>>>(x, Wgate);
    finalize_kernel<<<1, 32>>>(out, out_size);
    assign_kernel<<<(T + 255) / 256, 256>>>();

    // M fastest in grid.x so concurrent blocks share the same weight tile (L2 reuse)
    dim3 g1(T / BM, IDIM / BN, NE);          // (32, 88, 8)
    gemm1_kernel<<<g1, 256>>>(x, Wg, Wu);

    dim3 g2(T / BM, H / BN, NE);             // (32, 64, 8)
    gemm2_kernel<<<g2, 256>>>(Wd, out);
}